// round 15
// baseline (speedup 1.0000x reference)
#include <cuda_runtime.h>

#define BB 64
#define NP 576
#define DD 512
#define MM 16
#define NS_STRIDE 132        // noun smem row stride in float4 units (S mod 8 == 4 -> conflict-free LDS.128)

__device__ float  g_scores[BB*BB];
__device__ float  g_pooled[BB*NP];
__device__ float  g_scaled[BB*MM*NP];   // sim / T  (n-major per (b,m))

// ---------------- helpers ----------------
__device__ __forceinline__ float dot4(float4 a, float4 b){
    return a.x*b.x + a.y*b.y + a.z*b.z + a.w*b.w;
}
__device__ __forceinline__ void top5_insert(float t[5], float a){
    #pragma unroll
    for (int q = 0; q < 5; ++q){
        float mx = fmaxf(t[q], a);
        a        = fminf(t[q], a);
        t[q] = mx;
    }
}
__device__ __forceinline__ float warp_top5_sum(float t[5], int lane, float* write5){
    float total = 0.0f;
    #pragma unroll
    for (int it = 0; it < 5; ++it){
        float v = t[0]; int who = lane;
        #pragma unroll
        for (int d = 16; d >= 1; d >>= 1){
            float ov = __shfl_xor_sync(0xffffffffu, v,   d);
            int   ow = __shfl_xor_sync(0xffffffffu, who, d);
            if (ov > v || (ov == v && ow < who)){ v = ov; who = ow; }
        }
        total += v;
        if (write5 && lane == 0) write5[it] = v;
        if (lane == who){ t[0]=t[1]; t[1]=t[2]; t[2]=t[3]; t[3]=t[4]; t[4]=-1e30f; }
    }
    return total;
}
// tf32 MMA: D(16x8,f32) += A(16x8) * B(8x8). fp32 bits passed as tf32 (HW truncates).
__device__ __forceinline__ void mma_tf32(float c[4], float a0, float a1, float a2, float a3,
                                         float b0, float b1){
    asm volatile(
        "mma.sync.aligned.m16n8k8.row.col.f32.tf32.tf32.f32 "
        "{%0,%1,%2,%3}, {%4,%5,%6,%7}, {%8,%9}, {%0,%1,%2,%3};"
        : "+f"(c[0]), "+f"(c[1]), "+f"(c[2]), "+f"(c[3])
        : "r"(__float_as_uint(a0)), "r"(__float_as_uint(a1)),
          "r"(__float_as_uint(a2)), "r"(__float_as_uint(a3)),
          "r"(__float_as_uint(b0)), "r"(__float_as_uint(b1)));
}
// PDL controls
__device__ __forceinline__ void pdl_trigger(){
    asm volatile("griddepcontrol.launch_dependents;");
}
__device__ __forceinline__ void pdl_wait(){
    asm volatile("griddepcontrol.wait;" ::: "memory");
}

// =======================================================================
// Kernel 1: grid (13,64), 192 thr. Split-K warp pairs: 3 pairs x 16 patches.
//   bx in [0,12): 48 patches x 16 nouns; warp parity = K-half (256 each)
//   bx == 12  : row b of global scores; b==0 also zeroes out[0..2]
// =======================================================================
__global__ __launch_bounds__(192, 4)
void k_sim(const float* __restrict__ patch, const float* __restrict__ noun,
           const float* __restrict__ img,   const float* __restrict__ txt,
           float* __restrict__ out){
    __shared__ float4 ns[MM * NS_STRIDE];   // 16 rows x 132 float4 = 33792 B
    __shared__ float4 reds[3][32][2];       // odd-warp partial accums (3 KB)

    const int b    = blockIdx.y;
    const int lane = threadIdx.x & 31;
    const int w    = threadIdx.x >> 5;       // 0..5

    if (blockIdx.x == 12){
        if (b == 0 && threadIdx.x == 0){
            out[0] = 0.0f; out[1] = 0.0f; out[2] = 0.0f;
        }
        const float4* ip = reinterpret_cast<const float4*>(img + (size_t)b * DD);
        float4 a0 = ip[lane], a1 = ip[lane+32], a2 = ip[lane+64], a3 = ip[lane+96];
        for (int j = w; j < BB; j += 6){
            const float4* tp = reinterpret_cast<const float4*>(txt + (size_t)j * DD);
            float s = dot4(a0, tp[lane]) + dot4(a1, tp[lane+32])
                    + dot4(a2, tp[lane+64]) + dot4(a3, tp[lane+96]);
            #pragma unroll
            for (int d = 16; d >= 1; d >>= 1) s += __shfl_xor_sync(0xffffffffu, s, d);
            if (lane == 0) g_scores[b * BB + j] = s;
        }
        pdl_trigger();
        return;
    }

    // ---- load noun tile (16 x 512 floats) into padded SMEM ----
    {
        const float4* np = reinterpret_cast<const float4*>(noun + (size_t)b * MM * DD);
        #pragma unroll
        for (int i = threadIdx.x; i < MM * (DD/4); i += 192){
            int r = i >> 7;            // 128 float4 per row
            int j = i & 127;
            ns[r * NS_STRIDE + j] = np[i];
        }
    }
    __syncthreads();

    const int q   = lane & 3;       // col-group / k-selector
    const int gid = lane >> 2;      // row-group / noun-selector
    const int u   = w >> 1;         // pair index 0..2
    const int h   = w & 1;          // K-half
    const int rowbase = blockIdx.x * 48 + u * 16;
    const int row0 = rowbase + gid;

    const float4* Alo = reinterpret_cast<const float4*>(patch + ((size_t)b*NP + row0) * DD);
    const float4* Ahi = Alo + 8 * (DD/4);
    const float4* B0s = ns + gid * NS_STRIDE;
    const float4* B1s = ns + (gid + 8) * NS_STRIDE;

    float cH0[4] = {0,0,0,0};   // nouns 0..7
    float cH1[4] = {0,0,0,0};   // nouns 8..15

    // This warp covers K float4-indices {4p+q : p in [16h, 16h+16)}.
    const int pbase = 16 * h;
    #pragma unroll 4
    for (int p = 0; p < 16; ++p){
        const int o = 4*(pbase + p) + q;
        float4 alo = Alo[o];
        float4 ahi = Ahi[o];
        float4 b0  = B0s[o];
        float4 b1  = B1s[o];
        mma_tf32(cH0, alo.x, ahi.x, alo.y, ahi.y, b0.x, b0.y);
        mma_tf32(cH1, alo.x, ahi.x, alo.y, ahi.y, b1.x, b1.y);
        mma_tf32(cH0, alo.z, ahi.z, alo.w, ahi.w, b0.z, b0.w);
        mma_tf32(cH1, alo.z, ahi.z, alo.w, ahi.w, b1.z, b1.w);
    }

    // ---- combine K-halves: odd warp -> smem, even warp adds ----
    if (h == 1){
        reds[u][lane][0] = make_float4(cH0[0], cH0[1], cH0[2], cH0[3]);
        reds[u][lane][1] = make_float4(cH1[0], cH1[1], cH1[2], cH1[3]);
    }
    __syncthreads();
    if (h == 1){ pdl_trigger(); return; }

    {
        float4 p0 = reds[u][lane][0];
        float4 p1 = reds[u][lane][1];
        cH0[0] += p0.x; cH0[1] += p0.y; cH0[2] += p0.z; cH0[3] += p0.w;
        cH1[0] += p1.x; cH1[1] += p1.y; cH1[2] += p1.z; cH1[3] += p1.w;
    }

    const float INVT = (float)(1.0 / 0.07);
    #pragma unroll
    for (int i = 0; i < 4; ++i){ cH0[i] *= INVT; cH1[i] *= INVT; }

    // C layout: c[0]=C[gid][2q] c[1]=C[gid][2q+1] c[2]=C[gid+8][2q] c[3]=C[gid+8][2q+1]
    {
        float* base0 = g_scaled + ((size_t)b * MM) * NP + rowbase;
        base0[(2*q    ) * NP + gid    ] = cH0[0];
        base0[(2*q    ) * NP + gid + 8] = cH0[2];
        base0[(2*q + 1) * NP + gid    ] = cH0[1];
        base0[(2*q + 1) * NP + gid + 8] = cH0[3];
        base0[(2*q + 8) * NP + gid    ] = cH1[0];
        base0[(2*q + 8) * NP + gid + 8] = cH1[2];
        base0[(2*q + 9) * NP + gid    ] = cH1[1];
        base0[(2*q + 9) * NP + gid + 8] = cH1[3];
    }

    // pooled row sums over all 16 nouns (scaled space)
    float r0 = cH0[0] + cH0[1] + cH1[0] + cH1[1];
    float r1 = cH0[2] + cH0[3] + cH1[2] + cH1[3];
    r0 += __shfl_xor_sync(0xffffffffu, r0, 1);
    r0 += __shfl_xor_sync(0xffffffffu, r0, 2);
    r1 += __shfl_xor_sync(0xffffffffu, r1, 1);
    r1 += __shfl_xor_sync(0xffffffffu, r1, 2);
    if (q == 0){
        g_pooled[b * NP + rowbase + gid]     = r0 * (1.0f/16.0f);
        g_pooled[b * NP + rowbase + gid + 8] = r1 * (1.0f/16.0f);
    }
    pdl_trigger();
}

// =======================================================================
// Kernel 2 (final): grid 68, 768 threads (24 warps). PDL-overlapped launch.
//  blocks 0..63 : batch b fine-grained stats -> atomicAdd(out[2], scaled term)
//  blocks 64..67: contrastive + triplet (16 rows/block) -> out[0], out[1]
// =======================================================================
__global__ __launch_bounds__(768)
void k_tail(const float* __restrict__ logit_scale, const int* __restrict__ idx,
            float* __restrict__ out){
    const int lane = threadIdx.x & 31;
    const int w    = threadIdx.x >> 5;     // 0..23
    const int tid  = threadIdx.x;

    if (blockIdx.x < 64){
        const int b = blockIdx.x;
        __shared__ float s_red[16];
        __shared__ float s_sp[8];
        __shared__ float s_top[8 * 5];

        pdl_wait();   // k_sim results needed below

        if (w < 16){
            // ---- part A: noun m = w, stats over 576 sims (18 per lane) ----
            const float* row = g_scaled + ((size_t)b * MM + w) * NP;
            float se = 0.0f;
            float t [5] = {-1e30f, -1e30f, -1e30f, -1e30f, -1e30f};
            float t2[5] = {-1e30f, -1e30f, -1e30f, -1e30f, -1e30f};
            #pragma unroll
            for (int r = 0; r < 18; r += 2){
                float x0 = row[lane + r * 32];
                float x1 = row[lane + (r + 1) * 32];
                se += __expf(x0) + __expf(x1);   // max-free: |x| <= ~14.3
                top5_insert(t,  x0);
                top5_insert(t2, x1);
            }
            #pragma unroll
            for (int i = 0; i < 5; ++i) top5_insert(t, t2[i]);
            #pragma unroll
            for (int d = 16; d >= 1; d >>= 1) se += __shfl_xor_sync(0xffffffffu, se, d);
            float tsum = warp_top5_sum(t, lane, nullptr);
            if (lane == 0) s_red[w] = 5.0f * __logf(se) - tsum;
        } else {
            // ---- part B: warp wb = w-16 handles 72 pooled values ----
            const int wb = w - 16;
            const float* pb = g_pooled + b * NP + wb * 72;
            float u[5] = {-1e30f, -1e30f, -1e30f, -1e30f, -1e30f};
            float sp = 0.0f;
            float x0 = pb[lane];
            float x1 = pb[lane + 32];
            sp += fmaxf(x0, 0.0f) + __logf(1.0f + __expf(-fabsf(x0)));
            sp += fmaxf(x1, 0.0f) + __logf(1.0f + __expf(-fabsf(x1)));
            top5_insert(u, x0); top5_insert(u, x1);
            if (lane < 8){
                float x2 = pb[lane + 64];
                sp += fmaxf(x2, 0.0f) + __logf(1.0f + __expf(-fabsf(x2)));
                top5_insert(u, x2);
            }
            #pragma unroll
            for (int d = 16; d >= 1; d >>= 1) sp += __shfl_xor_sync(0xffffffffu, sp, d);
            if (lane == 0) s_sp[wb] = sp;
            warp_top5_sum(u, lane, &s_top[wb * 5]);
        }
        __syncthreads();

        if (w == 0){
            float qq[5] = {-1e30f, -1e30f, -1e30f, -1e30f, -1e30f};
            top5_insert(qq, s_top[lane]);
            if (lane < 8) top5_insert(qq, s_top[lane + 32]);
            float ftop = warp_top5_sum(qq, lane, nullptr);

            float crt = (lane < 16) ? s_red[lane] : 0.0f;
            float spt = (lane < 8)  ? s_sp[lane]  : 0.0f;
            #pragma unroll
            for (int d = 16; d >= 1; d >>= 1){
                crt += __shfl_xor_sync(0xffffffffu, crt, d);
                spt += __shfl_xor_sync(0xffffffffu, spt, d);
            }
            if (lane == 0){
                float term = crt * (0.6f / (float)(BB * MM))
                           + (spt - ftop) * (0.4f / (float)(BB * NP));
                atomicAdd(&out[2], term);
            }
        }
        return;
    }

    // ---------------- contrastive + triplet block ----------------
    __shared__ int   sidx[64];
    __shared__ float s_c[16];
    __shared__ float s_t[16];
    if (tid < 64) sidx[tid] = idx[tid];   // harness input, safe pre-wait
    __syncthreads();
    pdl_wait();                           // g_scores needed below

    if (w < 16){
        const int r = (blockIdx.x - 64) * 16 + w;
        const float s = logit_scale[0];
        const int myid = sidx[r];
        const bool m1 = (sidx[lane]      == myid);
        const bool m2 = (sidx[lane + 32] == myid);

        // row r of logits
        float v1 = g_scores[r * BB + lane];
        float v2 = g_scores[r * BB + lane + 32];
        float l1 = s * v1, l2 = s * v2;
        float rs = __expf(l1) + __expf(l2);
        float rm = (m1 ? l1 : 0.0f) + (m2 ? l2 : 0.0f);
        float rc = (float)(m1 + m2);
        // column r of logits
        float c1 = s * g_scores[lane * BB + r];
        float c2 = s * g_scores[(lane + 32) * BB + r];
        float cs = __expf(c1) + __expf(c2);
        float cm = (m1 ? c1 : 0.0f) + (m2 ? c2 : 0.0f);
        // triplet row r
        float dr = g_scores[r * BB + r];
        float d1 = g_scores[lane * BB + lane];
        float d2 = g_scores[(lane + 32) * BB + lane + 32];
        float mt = 0.0f;
        if (lane != r)        mt += fmaxf(0.0f, 0.1f + v1 - dr) + fmaxf(0.0f, 0.1f + v1 - d1);
        if (lane + 32 != r)   mt += fmaxf(0.0f, 0.1f + v2 - dr) + fmaxf(0.0f, 0.1f + v2 - d2);

        #pragma unroll
        for (int d = 16; d >= 1; d >>= 1){
            rs += __shfl_xor_sync(0xffffffffu, rs, d);
            rm += __shfl_xor_sync(0xffffffffu, rm, d);
            rc += __shfl_xor_sync(0xffffffffu, rc, d);
            cs += __shfl_xor_sync(0xffffffffu, cs, d);
            cm += __shfl_xor_sync(0xffffffffu, cm, d);
            mt += __shfl_xor_sync(0xffffffffu, mt, d);
        }
        if (lane == 0){
            float li2t = __logf(rs) - rm / rc;
            float lt2i = __logf(cs) - cm / rc;
            s_c[w] = 0.5f * (li2t + lt2i);
            s_t[w] = mt;
        }
    }
    __syncthreads();

    if (w == 0){
        float cc = (lane < 16) ? s_c[lane] : 0.0f;
        float tt = (lane < 16) ? s_t[lane] : 0.0f;
        #pragma unroll
        for (int d = 16; d >= 1; d >>= 1){
            cc += __shfl_xor_sync(0xffffffffu, cc, d);
            tt += __shfl_xor_sync(0xffffffffu, tt, d);
        }
        if (lane == 0){
            atomicAdd(&out[0], cc * (1.0f / 64.0f));
            atomicAdd(&out[1], 0.5f * tt);
        }
    }
}

// =======================================================================
extern "C" void kernel_launch(void* const* d_in, const int* in_sizes, int n_in,
                              void* d_out, int out_size){
    (void)in_sizes; (void)n_in; (void)out_size;
    const float* patch = (const float*)d_in[0];
    const float* noun  = (const float*)d_in[1];
    const float* img   = (const float*)d_in[2];
    const float* txt   = (const float*)d_in[3];
    const float* lsc   = (const float*)d_in[4];
    const int*   idx   = (const int*)d_in[5];
    float* out = (float*)d_out;

    dim3 gsim(13, 64);
    k_sim<<<gsim, 192>>>(patch, noun, img, txt, out);

    // PDL launch of k_tail: overlaps its launch/setup with k_sim execution.
    cudaLaunchConfig_t cfg = {};
    cfg.gridDim  = dim3(68);
    cfg.blockDim = dim3(768);
    cfg.dynamicSmemBytes = 0;
    cfg.stream = 0;
    cudaLaunchAttribute attrs[1];
    attrs[0].id = cudaLaunchAttributeProgrammaticStreamSerialization;
    attrs[0].val.programmaticStreamSerializationAllowed = 1;
    cfg.attrs = attrs;
    cfg.numAttrs = 1;
    cudaLaunchKernelEx(&cfg, k_tail, lsc, idx, out);
}

// round 16
// speedup vs baseline: 1.1152x; 1.1152x over previous
#include <cuda_runtime.h>

#define BB 64
#define NP 576
#define DD 512
#define MM 16
#define NS_STRIDE 132        // noun smem row stride in float4 units (S mod 8 == 4 -> conflict-free LDS.128)

__device__ float  g_scores[BB*BB];
__device__ float  g_pooled[BB*NP];
__device__ float  g_scaled[BB*MM*NP];   // sim / T  (n-major per (b,m))

// ---------------- helpers ----------------
__device__ __forceinline__ float dot4(float4 a, float4 b){
    return a.x*b.x + a.y*b.y + a.z*b.z + a.w*b.w;
}
__device__ __forceinline__ void top5_insert(float t[5], float a){
    #pragma unroll
    for (int q = 0; q < 5; ++q){
        float mx = fmaxf(t[q], a);
        a        = fminf(t[q], a);
        t[q] = mx;
    }
}
__device__ __forceinline__ float warp_top5_sum(float t[5], int lane, float* write5){
    float total = 0.0f;
    #pragma unroll
    for (int it = 0; it < 5; ++it){
        float v = t[0]; int who = lane;
        #pragma unroll
        for (int d = 16; d >= 1; d >>= 1){
            float ov = __shfl_xor_sync(0xffffffffu, v,   d);
            int   ow = __shfl_xor_sync(0xffffffffu, who, d);
            if (ov > v || (ov == v && ow < who)){ v = ov; who = ow; }
        }
        total += v;
        if (write5 && lane == 0) write5[it] = v;
        if (lane == who){ t[0]=t[1]; t[1]=t[2]; t[2]=t[3]; t[3]=t[4]; t[4]=-1e30f; }
    }
    return total;
}
// tf32 MMA: D(16x8,f32) += A(16x8) * B(8x8). fp32 bits passed as tf32 (HW truncates).
__device__ __forceinline__ void mma_tf32(float c[4], float a0, float a1, float a2, float a3,
                                         float b0, float b1){
    asm volatile(
        "mma.sync.aligned.m16n8k8.row.col.f32.tf32.tf32.f32 "
        "{%0,%1,%2,%3}, {%4,%5,%6,%7}, {%8,%9}, {%0,%1,%2,%3};"
        : "+f"(c[0]), "+f"(c[1]), "+f"(c[2]), "+f"(c[3])
        : "r"(__float_as_uint(a0)), "r"(__float_as_uint(a1)),
          "r"(__float_as_uint(a2)), "r"(__float_as_uint(a3)),
          "r"(__float_as_uint(b0)), "r"(__float_as_uint(b1)));
}
// PDL controls
__device__ __forceinline__ void pdl_trigger(){
    asm volatile("griddepcontrol.launch_dependents;");
}
__device__ __forceinline__ void pdl_wait(){
    asm volatile("griddepcontrol.wait;" ::: "memory");
}

// =======================================================================
// Kernel 1: grid (7,64), 192 thr. Noun tile in SMEM; A-loads batched x8.
//   bx in [0,6): 96 patches x 16 nouns (16 patches/warp, 8 acc regs)
//   bx == 6   : row b of global scores; b==0 also zeroes out[0..2]
// =======================================================================
__global__ __launch_bounds__(192, 3)
void k_sim(const float* __restrict__ patch, const float* __restrict__ noun,
           const float* __restrict__ img,   const float* __restrict__ txt,
           float* __restrict__ out){
    __shared__ float4 ns[MM * NS_STRIDE];   // 16 rows x 132 float4 = 33792 B

    const int b    = blockIdx.y;
    const int lane = threadIdx.x & 31;
    const int w    = threadIdx.x >> 5;       // 0..5

    if (blockIdx.x == 6){
        if (b == 0 && threadIdx.x == 0){
            out[0] = 0.0f; out[1] = 0.0f; out[2] = 0.0f;
        }
        const float4* ip = reinterpret_cast<const float4*>(img + (size_t)b * DD);
        float4 a0 = ip[lane], a1 = ip[lane+32], a2 = ip[lane+64], a3 = ip[lane+96];
        for (int j = w; j < BB; j += 6){
            const float4* tp = reinterpret_cast<const float4*>(txt + (size_t)j * DD);
            float s = dot4(a0, tp[lane]) + dot4(a1, tp[lane+32])
                    + dot4(a2, tp[lane+64]) + dot4(a3, tp[lane+96]);
            #pragma unroll
            for (int d = 16; d >= 1; d >>= 1) s += __shfl_xor_sync(0xffffffffu, s, d);
            if (lane == 0) g_scores[b * BB + j] = s;
        }
        pdl_trigger();
        return;
    }

    // ---- load noun tile (16 x 512 floats) into padded SMEM ----
    {
        const float4* np = reinterpret_cast<const float4*>(noun + (size_t)b * MM * DD);
        #pragma unroll
        for (int i = threadIdx.x; i < MM * (DD/4); i += 192){
            int r = i >> 7;            // 128 float4 per row
            int j = i & 127;
            ns[r * NS_STRIDE + j] = np[i];
        }
    }
    __syncthreads();

    const int q   = lane & 3;       // col-group / k-selector
    const int gid = lane >> 2;      // row-group / noun-selector
    const int rowbase = blockIdx.x * 96 + w * 16;
    const int row0 = rowbase + gid;

    const float4* Alo = reinterpret_cast<const float4*>(patch + ((size_t)b*NP + row0) * DD);
    const float4* Ahi = Alo + 8 * (DD/4);
    const float4* B0s = ns + gid * NS_STRIDE;
    const float4* B1s = ns + (gid + 8) * NS_STRIDE;

    float cH0[4] = {0,0,0,0};   // nouns 0..7
    float cH1[4] = {0,0,0,0};   // nouns 8..15

    // K permutation inside each 16-col window: thread q owns cols 16p+4q..+3.
    // A-loads batched 8 iterations ahead to raise per-warp memory-level parallelism.
    for (int pp = 0; pp < 32; pp += 8){
        float4 areg[16];
        #pragma unroll
        for (int k = 0; k < 8; ++k){
            const int o = 4*(pp + k) + q;
            areg[2*k]     = Alo[o];
            areg[2*k + 1] = Ahi[o];
        }
        #pragma unroll
        for (int k = 0; k < 8; ++k){
            const int o = 4*(pp + k) + q;
            float4 alo = areg[2*k];
            float4 ahi = areg[2*k + 1];
            float4 b0  = B0s[o];
            float4 b1  = B1s[o];
            mma_tf32(cH0, alo.x, ahi.x, alo.y, ahi.y, b0.x, b0.y);
            mma_tf32(cH1, alo.x, ahi.x, alo.y, ahi.y, b1.x, b1.y);
            mma_tf32(cH0, alo.z, ahi.z, alo.w, ahi.w, b0.z, b0.w);
            mma_tf32(cH1, alo.z, ahi.z, alo.w, ahi.w, b1.z, b1.w);
        }
    }

    const float INVT = (float)(1.0 / 0.07);
    #pragma unroll
    for (int i = 0; i < 4; ++i){ cH0[i] *= INVT; cH1[i] *= INVT; }

    // C layout: c[0]=C[gid][2q] c[1]=C[gid][2q+1] c[2]=C[gid+8][2q] c[3]=C[gid+8][2q+1]
    {
        float* base0 = g_scaled + ((size_t)b * MM) * NP + rowbase;
        base0[(2*q    ) * NP + gid    ] = cH0[0];
        base0[(2*q    ) * NP + gid + 8] = cH0[2];
        base0[(2*q + 1) * NP + gid    ] = cH0[1];
        base0[(2*q + 1) * NP + gid + 8] = cH0[3];
        base0[(2*q + 8) * NP + gid    ] = cH1[0];
        base0[(2*q + 8) * NP + gid + 8] = cH1[2];
        base0[(2*q + 9) * NP + gid    ] = cH1[1];
        base0[(2*q + 9) * NP + gid + 8] = cH1[3];
    }

    // pooled row sums over all 16 nouns (scaled space)
    float r0 = cH0[0] + cH0[1] + cH1[0] + cH1[1];
    float r1 = cH0[2] + cH0[3] + cH1[2] + cH1[3];
    r0 += __shfl_xor_sync(0xffffffffu, r0, 1);
    r0 += __shfl_xor_sync(0xffffffffu, r0, 2);
    r1 += __shfl_xor_sync(0xffffffffu, r1, 1);
    r1 += __shfl_xor_sync(0xffffffffu, r1, 2);
    if (q == 0){
        g_pooled[b * NP + rowbase + gid]     = r0 * (1.0f/16.0f);
        g_pooled[b * NP + rowbase + gid + 8] = r1 * (1.0f/16.0f);
    }
    pdl_trigger();
}

// =======================================================================
// Kernel 2 (final): grid 68, 768 threads (24 warps). PDL-overlapped launch.
//  blocks 0..63 : batch b fine-grained stats -> atomicAdd(out[2], scaled term)
//  blocks 64..67: contrastive + triplet (16 rows/block) -> out[0], out[1]
// =======================================================================
__global__ __launch_bounds__(768)
void k_tail(const float* __restrict__ logit_scale, const int* __restrict__ idx,
            float* __restrict__ out){
    const int lane = threadIdx.x & 31;
    const int w    = threadIdx.x >> 5;     // 0..23
    const int tid  = threadIdx.x;

    if (blockIdx.x < 64){
        const int b = blockIdx.x;
        __shared__ float s_red[16];
        __shared__ float s_sp[8];
        __shared__ float s_top[8 * 5];

        pdl_wait();   // k_sim results needed below

        if (w < 16){
            // ---- part A: noun m = w, stats over 576 sims (18 per lane) ----
            const float* row = g_scaled + ((size_t)b * MM + w) * NP;
            float se = 0.0f;
            float t [5] = {-1e30f, -1e30f, -1e30f, -1e30f, -1e30f};
            float t2[5] = {-1e30f, -1e30f, -1e30f, -1e30f, -1e30f};
            #pragma unroll
            for (int r = 0; r < 18; r += 2){
                float x0 = row[lane + r * 32];
                float x1 = row[lane + (r + 1) * 32];
                se += __expf(x0) + __expf(x1);   // max-free: |x| <= ~14.3
                top5_insert(t,  x0);
                top5_insert(t2, x1);
            }
            #pragma unroll
            for (int i = 0; i < 5; ++i) top5_insert(t, t2[i]);
            #pragma unroll
            for (int d = 16; d >= 1; d >>= 1) se += __shfl_xor_sync(0xffffffffu, se, d);
            float tsum = warp_top5_sum(t, lane, nullptr);
            if (lane == 0) s_red[w] = 5.0f * __logf(se) - tsum;
        } else {
            // ---- part B: warp wb = w-16 handles 72 pooled values ----
            const int wb = w - 16;
            const float* pb = g_pooled + b * NP + wb * 72;
            float u[5] = {-1e30f, -1e30f, -1e30f, -1e30f, -1e30f};
            float sp = 0.0f;
            float x0 = pb[lane];
            float x1 = pb[lane + 32];
            sp += fmaxf(x0, 0.0f) + __logf(1.0f + __expf(-fabsf(x0)));
            sp += fmaxf(x1, 0.0f) + __logf(1.0f + __expf(-fabsf(x1)));
            top5_insert(u, x0); top5_insert(u, x1);
            if (lane < 8){
                float x2 = pb[lane + 64];
                sp += fmaxf(x2, 0.0f) + __logf(1.0f + __expf(-fabsf(x2)));
                top5_insert(u, x2);
            }
            #pragma unroll
            for (int d = 16; d >= 1; d >>= 1) sp += __shfl_xor_sync(0xffffffffu, sp, d);
            if (lane == 0) s_sp[wb] = sp;
            warp_top5_sum(u, lane, &s_top[wb * 5]);
        }
        __syncthreads();

        if (w == 0){
            float qq[5] = {-1e30f, -1e30f, -1e30f, -1e30f, -1e30f};
            top5_insert(qq, s_top[lane]);
            if (lane < 8) top5_insert(qq, s_top[lane + 32]);
            float ftop = warp_top5_sum(qq, lane, nullptr);

            float crt = (lane < 16) ? s_red[lane] : 0.0f;
            float spt = (lane < 8)  ? s_sp[lane]  : 0.0f;
            #pragma unroll
            for (int d = 16; d >= 1; d >>= 1){
                crt += __shfl_xor_sync(0xffffffffu, crt, d);
                spt += __shfl_xor_sync(0xffffffffu, spt, d);
            }
            if (lane == 0){
                float term = crt * (0.6f / (float)(BB * MM))
                           + (spt - ftop) * (0.4f / (float)(BB * NP));
                atomicAdd(&out[2], term);
            }
        }
        return;
    }

    // ---------------- contrastive + triplet block ----------------
    __shared__ int   sidx[64];
    __shared__ float s_c[16];
    __shared__ float s_t[16];
    if (tid < 64) sidx[tid] = idx[tid];   // harness input, safe pre-wait
    __syncthreads();
    pdl_wait();                           // g_scores needed below

    if (w < 16){
        const int r = (blockIdx.x - 64) * 16 + w;
        const float s = logit_scale[0];
        const int myid = sidx[r];
        const bool m1 = (sidx[lane]      == myid);
        const bool m2 = (sidx[lane + 32] == myid);

        // row r of logits
        float v1 = g_scores[r * BB + lane];
        float v2 = g_scores[r * BB + lane + 32];
        float l1 = s * v1, l2 = s * v2;
        float rs = __expf(l1) + __expf(l2);
        float rm = (m1 ? l1 : 0.0f) + (m2 ? l2 : 0.0f);
        float rc = (float)(m1 + m2);
        // column r of logits
        float c1 = s * g_scores[lane * BB + r];
        float c2 = s * g_scores[(lane + 32) * BB + r];
        float cs = __expf(c1) + __expf(c2);
        float cm = (m1 ? c1 : 0.0f) + (m2 ? c2 : 0.0f);
        // triplet row r
        float dr = g_scores[r * BB + r];
        float d1 = g_scores[lane * BB + lane];
        float d2 = g_scores[(lane + 32) * BB + lane + 32];
        float mt = 0.0f;
        if (lane != r)        mt += fmaxf(0.0f, 0.1f + v1 - dr) + fmaxf(0.0f, 0.1f + v1 - d1);
        if (lane + 32 != r)   mt += fmaxf(0.0f, 0.1f + v2 - dr) + fmaxf(0.0f, 0.1f + v2 - d2);

        #pragma unroll
        for (int d = 16; d >= 1; d >>= 1){
            rs += __shfl_xor_sync(0xffffffffu, rs, d);
            rm += __shfl_xor_sync(0xffffffffu, rm, d);
            rc += __shfl_xor_sync(0xffffffffu, rc, d);
            cs += __shfl_xor_sync(0xffffffffu, cs, d);
            cm += __shfl_xor_sync(0xffffffffu, cm, d);
            mt += __shfl_xor_sync(0xffffffffu, mt, d);
        }
        if (lane == 0){
            float li2t = __logf(rs) - rm / rc;
            float lt2i = __logf(cs) - cm / rc;
            s_c[w] = 0.5f * (li2t + lt2i);
            s_t[w] = mt;
        }
    }
    __syncthreads();

    if (w == 0){
        float cc = (lane < 16) ? s_c[lane] : 0.0f;
        float tt = (lane < 16) ? s_t[lane] : 0.0f;
        #pragma unroll
        for (int d = 16; d >= 1; d >>= 1){
            cc += __shfl_xor_sync(0xffffffffu, cc, d);
            tt += __shfl_xor_sync(0xffffffffu, tt, d);
        }
        if (lane == 0){
            atomicAdd(&out[0], cc * (1.0f / 64.0f));
            atomicAdd(&out[1], 0.5f * tt);
        }
    }
}

// =======================================================================
extern "C" void kernel_launch(void* const* d_in, const int* in_sizes, int n_in,
                              void* d_out, int out_size){
    (void)in_sizes; (void)n_in; (void)out_size;
    const float* patch = (const float*)d_in[0];
    const float* noun  = (const float*)d_in[1];
    const float* img   = (const float*)d_in[2];
    const float* txt   = (const float*)d_in[3];
    const float* lsc   = (const float*)d_in[4];
    const int*   idx   = (const int*)d_in[5];
    float* out = (float*)d_out;

    dim3 gsim(7, 64);
    k_sim<<<gsim, 192>>>(patch, noun, img, txt, out);

    // PDL launch of k_tail: overlaps its launch/setup with k_sim execution.
    cudaLaunchConfig_t cfg = {};
    cfg.gridDim  = dim3(68);
    cfg.blockDim = dim3(768);
    cfg.dynamicSmemBytes = 0;
    cfg.stream = 0;
    cudaLaunchAttribute attrs[1];
    attrs[0].id = cudaLaunchAttributeProgrammaticStreamSerialization;
    attrs[0].val.programmaticStreamSerializationAllowed = 1;
    cfg.attrs = attrs;
    cfg.numAttrs = 1;
    cudaLaunchKernelEx(&cfg, k_tail, lsc, idx, out);
}

// round 17
// speedup vs baseline: 1.2652x; 1.1345x over previous
#include <cuda_runtime.h>

#define BB 64
#define NP 576
#define DD 512
#define MM 16
#define NS_STRIDE 132        // noun smem row stride in float4 units (S mod 8 == 4 -> conflict-free LDS.128)

__device__ float  g_scores[BB*BB];
__device__ float  g_pooled[BB*NP];
__device__ float  g_scaled[BB*MM*NP];   // sim / T  (n-major per (b,m))

// ---------------- helpers ----------------
__device__ __forceinline__ float dot4(float4 a, float4 b){
    return a.x*b.x + a.y*b.y + a.z*b.z + a.w*b.w;
}
__device__ __forceinline__ void top5_insert(float t[5], float a){
    #pragma unroll
    for (int q = 0; q < 5; ++q){
        float mx = fmaxf(t[q], a);
        a        = fminf(t[q], a);
        t[q] = mx;
    }
}
__device__ __forceinline__ float warp_top5_sum(float t[5], int lane, float* write5){
    float total = 0.0f;
    #pragma unroll
    for (int it = 0; it < 5; ++it){
        float v = t[0]; int who = lane;
        #pragma unroll
        for (int d = 16; d >= 1; d >>= 1){
            float ov = __shfl_xor_sync(0xffffffffu, v,   d);
            int   ow = __shfl_xor_sync(0xffffffffu, who, d);
            if (ov > v || (ov == v && ow < who)){ v = ov; who = ow; }
        }
        total += v;
        if (write5 && lane == 0) write5[it] = v;
        if (lane == who){ t[0]=t[1]; t[1]=t[2]; t[2]=t[3]; t[3]=t[4]; t[4]=-1e30f; }
    }
    return total;
}
// tf32 MMA: D(16x8,f32) += A(16x8) * B(8x8). fp32 bits passed as tf32 (HW truncates).
__device__ __forceinline__ void mma_tf32(float c[4], float a0, float a1, float a2, float a3,
                                         float b0, float b1){
    asm volatile(
        "mma.sync.aligned.m16n8k8.row.col.f32.tf32.tf32.f32 "
        "{%0,%1,%2,%3}, {%4,%5,%6,%7}, {%8,%9}, {%0,%1,%2,%3};"
        : "+f"(c[0]), "+f"(c[1]), "+f"(c[2]), "+f"(c[3])
        : "r"(__float_as_uint(a0)), "r"(__float_as_uint(a1)),
          "r"(__float_as_uint(a2)), "r"(__float_as_uint(a3)),
          "r"(__float_as_uint(b0)), "r"(__float_as_uint(b1)));
}
// PDL controls
__device__ __forceinline__ void pdl_trigger(){
    asm volatile("griddepcontrol.launch_dependents;");
}
__device__ __forceinline__ void pdl_wait(){
    asm volatile("griddepcontrol.wait;" ::: "memory");
}

// =======================================================================
// Kernel 1 (R14-exact): grid (7,64), 192 thr. Noun tile in SMEM.
//   bx in [0,6): 96 patches x 16 nouns (16 patches/warp, 8 acc regs)
//   bx == 6   : row b of global scores; b==0 also zeroes out[0..2]
// =======================================================================
__global__ __launch_bounds__(192, 3)
void k_sim(const float* __restrict__ patch, const float* __restrict__ noun,
           const float* __restrict__ img,   const float* __restrict__ txt,
           float* __restrict__ out){
    __shared__ float4 ns[MM * NS_STRIDE];   // 16 rows x 132 float4 = 33792 B

    const int b    = blockIdx.y;
    const int lane = threadIdx.x & 31;
    const int w    = threadIdx.x >> 5;       // 0..5

    if (blockIdx.x == 6){
        if (b == 0 && threadIdx.x == 0){
            out[0] = 0.0f; out[1] = 0.0f; out[2] = 0.0f;
        }
        const float4* ip = reinterpret_cast<const float4*>(img + (size_t)b * DD);
        float4 a0 = ip[lane], a1 = ip[lane+32], a2 = ip[lane+64], a3 = ip[lane+96];
        for (int j = w; j < BB; j += 6){
            const float4* tp = reinterpret_cast<const float4*>(txt + (size_t)j * DD);
            float s = dot4(a0, tp[lane]) + dot4(a1, tp[lane+32])
                    + dot4(a2, tp[lane+64]) + dot4(a3, tp[lane+96]);
            #pragma unroll
            for (int d = 16; d >= 1; d >>= 1) s += __shfl_xor_sync(0xffffffffu, s, d);
            if (lane == 0) g_scores[b * BB + j] = s;
        }
        pdl_trigger();
        return;
    }

    // ---- load noun tile (16 x 512 floats) into padded SMEM ----
    {
        const float4* np = reinterpret_cast<const float4*>(noun + (size_t)b * MM * DD);
        #pragma unroll
        for (int i = threadIdx.x; i < MM * (DD/4); i += 192){
            int r = i >> 7;            // 128 float4 per row
            int j = i & 127;
            ns[r * NS_STRIDE + j] = np[i];
        }
    }
    __syncthreads();

    const int q   = lane & 3;       // col-group / k-selector
    const int gid = lane >> 2;      // row-group / noun-selector
    const int rowbase = blockIdx.x * 96 + w * 16;
    const int row0 = rowbase + gid;

    const float4* Alo = reinterpret_cast<const float4*>(patch + ((size_t)b*NP + row0) * DD);
    const float4* Ahi = Alo + 8 * (DD/4);
    const float4* B0s = ns + gid * NS_STRIDE;
    const float4* B1s = ns + (gid + 8) * NS_STRIDE;

    float cH0[4] = {0,0,0,0};   // nouns 0..7
    float cH1[4] = {0,0,0,0};   // nouns 8..15

    // K permutation inside each 16-col window: thread q owns cols 16p+4q..+3,
    // applied identically to A and B fragments -> contiguous float4 loads.
    #pragma unroll 4
    for (int p = 0; p < 32; ++p){
        const int o = 4*p + q;
        float4 alo = Alo[o];
        float4 ahi = Ahi[o];
        float4 b0  = B0s[o];
        float4 b1  = B1s[o];
        mma_tf32(cH0, alo.x, ahi.x, alo.y, ahi.y, b0.x, b0.y);
        mma_tf32(cH1, alo.x, ahi.x, alo.y, ahi.y, b1.x, b1.y);
        mma_tf32(cH0, alo.z, ahi.z, alo.w, ahi.w, b0.z, b0.w);
        mma_tf32(cH1, alo.z, ahi.z, alo.w, ahi.w, b1.z, b1.w);
    }

    const float INVT = (float)(1.0 / 0.07);
    #pragma unroll
    for (int i = 0; i < 4; ++i){ cH0[i] *= INVT; cH1[i] *= INVT; }

    // C layout: c[0]=C[gid][2q] c[1]=C[gid][2q+1] c[2]=C[gid+8][2q] c[3]=C[gid+8][2q+1]
    {
        float* base0 = g_scaled + ((size_t)b * MM) * NP + rowbase;
        base0[(2*q    ) * NP + gid    ] = cH0[0];
        base0[(2*q    ) * NP + gid + 8] = cH0[2];
        base0[(2*q + 1) * NP + gid    ] = cH0[1];
        base0[(2*q + 1) * NP + gid + 8] = cH0[3];
        base0[(2*q + 8) * NP + gid    ] = cH1[0];
        base0[(2*q + 8) * NP + gid + 8] = cH1[2];
        base0[(2*q + 9) * NP + gid    ] = cH1[1];
        base0[(2*q + 9) * NP + gid + 8] = cH1[3];
    }

    // pooled row sums over all 16 nouns (scaled space)
    float r0 = cH0[0] + cH0[1] + cH1[0] + cH1[1];
    float r1 = cH0[2] + cH0[3] + cH1[2] + cH1[3];
    r0 += __shfl_xor_sync(0xffffffffu, r0, 1);
    r0 += __shfl_xor_sync(0xffffffffu, r0, 2);
    r1 += __shfl_xor_sync(0xffffffffu, r1, 1);
    r1 += __shfl_xor_sync(0xffffffffu, r1, 2);
    if (q == 0){
        g_pooled[b * NP + rowbase + gid]     = r0 * (1.0f/16.0f);
        g_pooled[b * NP + rowbase + gid + 8] = r1 * (1.0f/16.0f);
    }
    pdl_trigger();
}

// =======================================================================
// Kernel 2 (final): grid 200, 256 threads (8 warps). Small independent blocks.
//  bx in [0,128) : part A, batch b = bx>>1, nouns m = (bx&1)*8 + w
//  bx in [128,192): part B pooled, batch b = bx-128
//  bx in [192,200): contrastive+triplet, rows r = (bx-192)*8 + w
// =======================================================================
__global__ __launch_bounds__(256)
void k_tail(const float* __restrict__ logit_scale, const int* __restrict__ idx,
            float* __restrict__ out){
    const int lane = threadIdx.x & 31;
    const int w    = threadIdx.x >> 5;     // 0..7
    const int tid  = threadIdx.x;
    const int bx   = blockIdx.x;

    if (bx < 128){
        // ---------------- part A: 8 nouns of one batch ----------------
        const int b = bx >> 1;
        const int m = (bx & 1) * 8 + w;
        __shared__ float s_red[8];

        pdl_wait();

        const float* row = g_scaled + ((size_t)b * MM + m) * NP;
        float se = 0.0f;
        float t [5] = {-1e30f, -1e30f, -1e30f, -1e30f, -1e30f};
        float t2[5] = {-1e30f, -1e30f, -1e30f, -1e30f, -1e30f};
        #pragma unroll
        for (int r = 0; r < 18; r += 2){
            float x0 = row[lane + r * 32];
            float x1 = row[lane + (r + 1) * 32];
            se += __expf(x0) + __expf(x1);   // max-free: |x| <= ~14.3
            top5_insert(t,  x0);
            top5_insert(t2, x1);
        }
        #pragma unroll
        for (int i = 0; i < 5; ++i) top5_insert(t, t2[i]);
        #pragma unroll
        for (int d = 16; d >= 1; d >>= 1) se += __shfl_xor_sync(0xffffffffu, se, d);
        float tsum = warp_top5_sum(t, lane, nullptr);
        if (lane == 0) s_red[w] = 5.0f * __logf(se) - tsum;
        __syncthreads();

        if (tid == 0){
            float crt = 0.0f;
            #pragma unroll
            for (int i = 0; i < 8; ++i) crt += s_red[i];
            atomicAdd(&out[2], crt * (0.6f / (float)(BB * MM)));
        }
        return;
    }

    if (bx < 192){
        // ---------------- part B: pooled softplus + top5 for batch b ----------------
        const int b = bx - 128;
        __shared__ float s_sp[8];
        __shared__ float s_top[8 * 5];

        pdl_wait();

        const float* pb = g_pooled + b * NP + w * 72;
        float u[5] = {-1e30f, -1e30f, -1e30f, -1e30f, -1e30f};
        float sp = 0.0f;
        float x0 = pb[lane];
        float x1 = pb[lane + 32];
        sp += fmaxf(x0, 0.0f) + __logf(1.0f + __expf(-fabsf(x0)));
        sp += fmaxf(x1, 0.0f) + __logf(1.0f + __expf(-fabsf(x1)));
        top5_insert(u, x0); top5_insert(u, x1);
        if (lane < 8){
            float x2 = pb[lane + 64];
            sp += fmaxf(x2, 0.0f) + __logf(1.0f + __expf(-fabsf(x2)));
            top5_insert(u, x2);
        }
        #pragma unroll
        for (int d = 16; d >= 1; d >>= 1) sp += __shfl_xor_sync(0xffffffffu, sp, d);
        if (lane == 0) s_sp[w] = sp;
        warp_top5_sum(u, lane, &s_top[w * 5]);
        __syncthreads();

        if (w == 0){
            float qq[5] = {-1e30f, -1e30f, -1e30f, -1e30f, -1e30f};
            top5_insert(qq, s_top[lane]);
            if (lane < 8) top5_insert(qq, s_top[lane + 32]);
            float ftop = warp_top5_sum(qq, lane, nullptr);

            float spt = (lane < 8) ? s_sp[lane] : 0.0f;
            #pragma unroll
            for (int d = 16; d >= 1; d >>= 1) spt += __shfl_xor_sync(0xffffffffu, spt, d);

            if (lane == 0)
                atomicAdd(&out[2], (spt - ftop) * (0.4f / (float)(BB * NP)));
        }
        return;
    }

    // ---------------- contrastive + triplet: 8 rows per block ----------------
    __shared__ int   sidx[64];
    __shared__ float s_c[8];
    __shared__ float s_t[8];
    if (tid < 64) sidx[tid] = idx[tid];   // harness input, safe pre-wait
    __syncthreads();
    pdl_wait();                           // g_scores needed below

    {
        const int r = (bx - 192) * 8 + w;
        const float s = logit_scale[0];
        const int myid = sidx[r];
        const bool m1 = (sidx[lane]      == myid);
        const bool m2 = (sidx[lane + 32] == myid);

        // row r of logits
        float v1 = g_scores[r * BB + lane];
        float v2 = g_scores[r * BB + lane + 32];
        float l1 = s * v1, l2 = s * v2;
        float rs = __expf(l1) + __expf(l2);
        float rm = (m1 ? l1 : 0.0f) + (m2 ? l2 : 0.0f);
        float rc = (float)(m1 + m2);
        // column r of logits
        float c1 = s * g_scores[lane * BB + r];
        float c2 = s * g_scores[(lane + 32) * BB + r];
        float cs = __expf(c1) + __expf(c2);
        float cm = (m1 ? c1 : 0.0f) + (m2 ? c2 : 0.0f);
        // triplet row r
        float dr = g_scores[r * BB + r];
        float d1 = g_scores[lane * BB + lane];
        float d2 = g_scores[(lane + 32) * BB + lane + 32];
        float mt = 0.0f;
        if (lane != r)        mt += fmaxf(0.0f, 0.1f + v1 - dr) + fmaxf(0.0f, 0.1f + v1 - d1);
        if (lane + 32 != r)   mt += fmaxf(0.0f, 0.1f + v2 - dr) + fmaxf(0.0f, 0.1f + v2 - d2);

        #pragma unroll
        for (int d = 16; d >= 1; d >>= 1){
            rs += __shfl_xor_sync(0xffffffffu, rs, d);
            rm += __shfl_xor_sync(0xffffffffu, rm, d);
            rc += __shfl_xor_sync(0xffffffffu, rc, d);
            cs += __shfl_xor_sync(0xffffffffu, cs, d);
            cm += __shfl_xor_sync(0xffffffffu, cm, d);
            mt += __shfl_xor_sync(0xffffffffu, mt, d);
        }
        if (lane == 0){
            float li2t = __logf(rs) - rm / rc;
            float lt2i = __logf(cs) - cm / rc;
            s_c[w] = 0.5f * (li2t + lt2i);
            s_t[w] = mt;
        }
    }
    __syncthreads();

    if (tid == 0){
        float cc = 0.0f, tt = 0.0f;
        #pragma unroll
        for (int i = 0; i < 8; ++i){ cc += s_c[i]; tt += s_t[i]; }
        atomicAdd(&out[0], cc * (1.0f / 64.0f));
        atomicAdd(&out[1], 0.5f * tt);
    }
}

// =======================================================================
extern "C" void kernel_launch(void* const* d_in, const int* in_sizes, int n_in,
                              void* d_out, int out_size){
    (void)in_sizes; (void)n_in; (void)out_size;
    const float* patch = (const float*)d_in[0];
    const float* noun  = (const float*)d_in[1];
    const float* img   = (const float*)d_in[2];
    const float* txt   = (const float*)d_in[3];
    const float* lsc   = (const float*)d_in[4];
    const int*   idx   = (const int*)d_in[5];
    float* out = (float*)d_out;

    dim3 gsim(7, 64);
    k_sim<<<gsim, 192>>>(patch, noun, img, txt, out);

    // PDL launch of k_tail: overlaps its launch/setup with k_sim execution.
    cudaLaunchConfig_t cfg = {};
    cfg.gridDim  = dim3(200);
    cfg.blockDim = dim3(256);
    cfg.dynamicSmemBytes = 0;
    cfg.stream = 0;
    cudaLaunchAttribute attrs[1];
    attrs[0].id = cudaLaunchAttributeProgrammaticStreamSerialization;
    attrs[0].val.programmaticStreamSerializationAllowed = 1;
    cfg.attrs = attrs;
    cfg.numAttrs = 1;
    cudaLaunchKernelEx(&cfg, k_tail, lsc, idx, out);
}